// round 8
// baseline (speedup 1.0000x reference)
#include <cuda_runtime.h>
#include <cuda_bf16.h>
#include <cuda_fp16.h>
#include <cstdint>
#include <math.h>

#define N_NODES   50000
#define NROWS     50048
#define N_EDGES   800000
#define NUM_GRAPHS 256
#define C         129
#define ZDIM      259
#define NLAYERS   5
#define XS        160
#define PLN       132
#define NCOL      264
#define NPG       288
#define P2S       320

// GEMM smem offsets
#define GSA    0
#define GSAL   43008
#define GSB    86016
#define GSSP   23040
#define GSBUF  46080
#define GSBI   178176
#define GSMEM  179328

__device__ __align__(16) __nv_bfloat16 d_wbN[NLAYERS*2*2*5*NPG*32];
__device__ float d_bph[NLAYERS*2*NPG];
__device__ float d_w3[NLAYERS*NCOL];
__device__ __align__(16) float d_xa[NROWS*XS];
__device__ __align__(16) float d_xb[NROWS*XS];
__device__ __align__(16) float  d_P1[(size_t)NROWS*NCOL];
__device__ __align__(16) __half d_P2h[(size_t)NROWS*P2S];
__device__ int   d_cnt[N_NODES];
__device__ int   d_rowptr[N_NODES + 1];
__device__ int   d_pos[N_NODES];
__device__ __align__(8) int2 d_edges[N_EDGES];   // (src, ea bits)
__device__ float d_gsum[NUM_GRAPHS*PLN];
__device__ float d_gcnt[NUM_GRAPHS];

__device__ __forceinline__ uint32_t smem_u32(const void* p){
    uint32_t a;
    asm("{ .reg .u64 t; cvta.to.shared.u64 t, %1; cvt.u32.u64 %0, t; }" : "=r"(a) : "l"(p));
    return a;
}
__device__ __forceinline__ void mma16816(float* d, uint32_t a0, uint32_t a1,
                                         uint32_t a2, uint32_t a3,
                                         uint32_t b0, uint32_t b1){
    asm volatile(
        "mma.sync.aligned.m16n8k16.row.col.f32.bf16.bf16.f32 "
        "{%0,%1,%2,%3}, {%4,%5,%6,%7}, {%8,%9}, {%0,%1,%2,%3};"
        : "+f"(d[0]), "+f"(d[1]), "+f"(d[2]), "+f"(d[3])
        : "r"(a0), "r"(a1), "r"(a2), "r"(a3), "r"(b0), "r"(b1));
}
__device__ __forceinline__ void cpasync16(uint32_t s, const void* g){
    asm volatile("cp.async.cg.shared.global [%0], [%1], 16;" :: "r"(s), "l"(g));
}
__device__ __forceinline__ void red4(float* p, float4 v){
    asm volatile("red.global.add.v4.f32 [%0], {%1,%2,%3,%4};"
                 :: "l"(p), "f"(v.x), "f"(v.y), "f"(v.z), "f"(v.w) : "memory");
}
__device__ __forceinline__ float sigf(float f){
    float t;
    asm("tanh.approx.f32 %0, %1;" : "=f"(t) : "f"(0.5f * f));
    return fmaf(0.5f, t, 0.5f);
}
__device__ __forceinline__ float gact(float f, float s){
    float sp = fmaxf(s, 0.f) + __logf(1.f + __expf(-fabsf(s)));
    return sigf(f) * sp;
}

// ---- prepack ----
__global__ void pack_wbN_kernel(const float* __restrict__ Wf, const float* __restrict__ Ws){
    int idx = blockIdx.x * blockDim.x + threadIdx.x;
    if (idx >= NLAYERS*2*2*5*NPG*32) return;
    int k  = idx & 31;
    int n  = (idx >> 5) % NPG;
    int kc = (idx / (32*NPG)) % 5;
    int sp = (idx / (32*NPG*5)) & 1;
    int hf = (idx / (32*NPG*5*2)) & 1;
    int l  = idx / (32*NPG*5*2*2);
    int kg = kc*32 + k;
    float w = 0.f;
    if (n < NCOL && kg < C){
        int plane = n / PLN, j = n % PLN;
        if (j < C){
            int zi = hf ? (C + kg) : kg;
            const float* W = plane ? Ws : Wf;
            w = W[(l*ZDIM + zi)*C + j];
        }
    }
    __nv_bfloat16 hi = __float2bfloat16(w);
    d_wbN[idx] = sp ? __float2bfloat16(w - __bfloat162float(hi)) : hi;
}
__global__ void pack_bph_kernel(const float* __restrict__ bf, const float* __restrict__ bs){
    int idx = blockIdx.x * blockDim.x + threadIdx.x;
    if (idx >= NLAYERS*2*NPG) return;
    int n = idx % NPG, hf = (idx / NPG) & 1, l = idx / (2*NPG);
    float v = 0.f;
    if (hf == 0 && n < NCOL){
        int plane = n / PLN, j = n % PLN;
        if (j < C) v = plane ? bs[l*C + j] : bf[l*C + j];
    }
    d_bph[idx] = v;
}
__global__ void pack_w3_kernel(const float* __restrict__ Wf, const float* __restrict__ Ws){
    int idx = blockIdx.x * blockDim.x + threadIdx.x;
    if (idx >= NLAYERS*NCOL) return;
    int n = idx % NCOL, l = idx / NCOL;
    int plane = n / PLN, j = n % PLN;
    float v = 0.f;
    if (j < C){ const float* W = plane ? Ws : Wf; v = W[(l*ZDIM + 258)*C + j]; }
    d_w3[idx] = v;
}
__global__ void init_x_kernel(const int* __restrict__ atoms, const float* __restrict__ pos,
                              const float* __restrict__ emb){
    int idx = blockIdx.x * blockDim.x + threadIdx.x;
    if (idx >= NROWS*XS) return;
    int n = idx / XS, c = idx - n*XS;
    float v = 0.f;
    if (n < N_NODES){
        if (c < 128) v = emb[atoms[n]*128 + c];
        else if (c == 128) v = pos[n*3 + 2];
    }
    d_xa[idx] = v;
}

// ---- CSR build ----
__global__ void zero_cnt_kernel(){
    int i = blockIdx.x * blockDim.x + threadIdx.x;
    if (i < N_NODES) d_cnt[i] = 0;
}
__global__ void hist_kernel(const int* __restrict__ ei){
    int e = blockIdx.x * blockDim.x + threadIdx.x;
    if (e < N_EDGES) atomicAdd(&d_cnt[ei[N_EDGES + e]], 1);
}
__global__ void scan_kernel(){
    __shared__ int wsum[32];
    __shared__ int carry;
    int tid = threadIdx.x, lane = tid & 31, wid = tid >> 5;
    if (tid == 0) carry = 0;
    __syncthreads();
    for (int base = 0; base < N_NODES; base += 1024){
        int i = base + tid;
        int v = (i < N_NODES) ? d_cnt[i] : 0;
        int x = v;
        #pragma unroll
        for (int d = 1; d < 32; d <<= 1){
            int y = __shfl_up_sync(0xffffffffu, x, d);
            if (lane >= d) x += y;
        }
        if (lane == 31) wsum[wid] = x;
        __syncthreads();
        if (wid == 0){
            int s = wsum[lane];
            #pragma unroll
            for (int d = 1; d < 32; d <<= 1){
                int y = __shfl_up_sync(0xffffffffu, s, d);
                if (lane >= d) s += y;
            }
            wsum[lane] = s;
        }
        __syncthreads();
        int excl = x - v + (wid ? wsum[wid-1] : 0) + carry;
        if (i < N_NODES){ d_rowptr[i] = excl; d_pos[i] = excl; }
        __syncthreads();
        if (tid == 0) carry += wsum[31];
        __syncthreads();
    }
    if (threadIdx.x == 0) d_rowptr[N_NODES] = carry;
}
__global__ void scatter_kernel(const int* __restrict__ ei, const float* __restrict__ pos){
    int e = blockIdx.x * blockDim.x + threadIdx.x;
    if (e >= N_EDGES) return;
    int s = ei[e], d = ei[N_EDGES + e];
    float dx = pos[s*3]-pos[d*3], dy = pos[s*3+1]-pos[d*3+1], dz = pos[s*3+2]-pos[d*3+2];
    float eav = sqrtf(dx*dx + dy*dy + dz*dz);
    int p = atomicAdd(&d_pos[d], 1);
    d_edges[p] = make_int2(s, __float_as_int(eav));
}

// ---- node GEMM ----
__global__ __launch_bounds__(512, 1)
void node_gemm_kernel(const float* __restrict__ xc, int layer){
    extern __shared__ __align__(16) char smem[];
    uint32_t sb = smem_u32(smem);
    int tid = threadIdx.x, lane = tid & 31, wid = tid >> 5;
    int r0 = lane >> 2, tin = lane & 3;
    int warpM = wid & 3, warpN = wid >> 2;
    int m0 = blockIdx.x * 128;
    int hf = blockIdx.y;

    const __nv_bfloat16* wbase = d_wbN + (size_t)((layer*2 + hf)*2) * 5*NPG*32;

    #pragma unroll
    for (int pc = 0; pc < 2; pc++){
        for (int i = tid; i < 2304; i += 512){
            int sp = i / 1152, rr = i % 1152, n = rr >> 2, kv = rr & 3;
            const void* g = wbase + ((size_t)sp*5 + pc)*NPG*32 + n*32 + kv*8;
            cpasync16(sb + GSB + pc*GSBUF + sp*GSSP + n*80 + kv*16, g);
        }
        asm volatile("cp.async.commit_group;" ::: "memory");
    }
    float* biS = (float*)(smem + GSBI);
    for (int i = tid; i < NPG; i += 512) biS[i] = d_bph[(layer*2 + hf)*NPG + i];

    {
        int row = tid >> 2, q = tid & 3;
        const float4* xr = (const float4*)(xc + (size_t)(m0 + row)*XS) + q*10;
        char* arow = smem + GSA + row*336 + q*80;
        #pragma unroll
        for (int j = 0; j < 10; j++){
            float4 v = xr[j];
            __nv_bfloat16 hx = __float2bfloat16(v.x), hy = __float2bfloat16(v.y);
            __nv_bfloat16 hz = __float2bfloat16(v.z), hw = __float2bfloat16(v.w);
            __nv_bfloat162 h0(hx, hy), h1(hz, hw);
            __nv_bfloat162 l0(__float2bfloat16(v.x - __bfloat162float(hx)),
                              __float2bfloat16(v.y - __bfloat162float(hy)));
            __nv_bfloat162 l1(__float2bfloat16(v.z - __bfloat162float(hz)),
                              __float2bfloat16(v.w - __bfloat162float(hw)));
            *(uint2*)(arow + j*8)        = make_uint2(*(uint32_t*)&h0, *(uint32_t*)&h1);
            *(uint2*)(arow + GSAL + j*8) = make_uint2(*(uint32_t*)&l0, *(uint32_t*)&l1);
        }
    }

    float acc[2][9][4];
    #pragma unroll
    for (int a = 0; a < 2; a++)
        #pragma unroll
        for (int b = 0; b < 9; b++)
            #pragma unroll
            for (int c = 0; c < 4; c++) acc[a][b][c] = 0.f;

    uint32_t aoff = (uint32_t)((warpM*32 + r0)*336 + tin*4);
    uint32_t boff = (uint32_t)((warpN*72 + r0)*80 + tin*4);

    for (int sc = 0; sc < 5; sc++){
        int buf = sc & 1;
        if (sc == 4) asm volatile("cp.async.wait_group 0;" ::: "memory");
        else         asm volatile("cp.async.wait_group 1;" ::: "memory");
        __syncthreads();
        const char* bbuf = smem + GSB + buf*GSBUF;
        #pragma unroll
        for (int ks = 0; ks < 2; ks++){
            uint32_t ka = (uint32_t)(sc*32 + ks*16)*2;
            const char* ap = smem + GSA + aoff + ka;
            uint32_t ah[2][4], al[2][4];
            #pragma unroll
            for (int mt = 0; mt < 2; mt++){
                const char* p = ap + mt*5376;
                ah[mt][0] = *(const uint32_t*)(p);
                ah[mt][1] = *(const uint32_t*)(p + 2688);
                ah[mt][2] = *(const uint32_t*)(p + 16);
                ah[mt][3] = *(const uint32_t*)(p + 2704);
                const char* q = p + GSAL;
                al[mt][0] = *(const uint32_t*)(q);
                al[mt][1] = *(const uint32_t*)(q + 2688);
                al[mt][2] = *(const uint32_t*)(q + 16);
                al[mt][3] = *(const uint32_t*)(q + 2704);
            }
            uint32_t kb = (uint32_t)ks*32;
            #pragma unroll
            for (int nt = 0; nt < 9; nt++){
                const char* bp = bbuf + boff + nt*640 + kb;
                uint32_t bh0 = *(const uint32_t*)(bp);
                uint32_t bh1 = *(const uint32_t*)(bp + 16);
                uint32_t bl0 = *(const uint32_t*)(bp + GSSP);
                uint32_t bl1 = *(const uint32_t*)(bp + GSSP + 16);
                mma16816(acc[0][nt], ah[0][0], ah[0][1], ah[0][2], ah[0][3], bh0, bh1);
                mma16816(acc[1][nt], ah[1][0], ah[1][1], ah[1][2], ah[1][3], bh0, bh1);
                mma16816(acc[0][nt], al[0][0], al[0][1], al[0][2], al[0][3], bh0, bh1);
                mma16816(acc[1][nt], al[1][0], al[1][1], al[1][2], al[1][3], bh0, bh1);
                mma16816(acc[0][nt], ah[0][0], ah[0][1], ah[0][2], ah[0][3], bl0, bl1);
                mma16816(acc[1][nt], ah[1][0], ah[1][1], ah[1][2], ah[1][3], bl0, bl1);
            }
        }
        __syncthreads();
        if (sc < 3){
            int nc = sc + 2;
            for (int i = tid; i < 2304; i += 512){
                int sp = i / 1152, rr = i % 1152, n = rr >> 2, kv = rr & 3;
                const void* g = wbase + ((size_t)sp*5 + nc)*NPG*32 + n*32 + kv*8;
                cpasync16(sb + GSB + buf*GSBUF + sp*GSSP + n*80 + kv*16, g);
            }
            asm volatile("cp.async.commit_group;" ::: "memory");
        }
    }

    #pragma unroll
    for (int mt = 0; mt < 2; mt++){
        #pragma unroll
        for (int nt = 0; nt < 9; nt++){
            int col = warpN*72 + nt*8 + tin*2;
            if (col >= NCOL) continue;
            float b0 = biS[col], b1 = biS[col + 1];
            #pragma unroll
            for (int h = 0; h < 2; h++){
                int row = m0 + warpM*32 + mt*16 + r0 + h*8;
                float v0 = acc[mt][nt][2*h] + b0;
                float v1 = acc[mt][nt][2*h+1] + b1;
                if (hf == 0){
                    *(float2*)(d_P1 + (size_t)row*NCOL + col) = make_float2(v0, v1);
                } else {
                    *(__half2*)(d_P2h + (size_t)row*P2S + col) = __floats2half2_rn(v0, v1);
                }
            }
        }
    }
}

// ---- edge phase: 2 warps/node, group-of-4 prefetched gathers ----
__global__ __launch_bounds__(256)
void edge_csr_kernel(const float* __restrict__ xc, float* __restrict__ xn, int layer){
    int lane = threadIdx.x & 31, warp = threadIdx.x >> 5;
    int n = blockIdx.x * 4 + (warp >> 1);
    int half = warp & 1;
    int ch = half*64 + lane*2;
    bool tail = (half == 1 && lane == 0);

    const float* w3 = d_w3 + layer * NCOL;
    float wf0 = w3[ch], wf1 = w3[ch+1];
    float ws0 = w3[PLN+ch], ws1 = w3[PLN+ch+1];
    const float* p1 = d_P1 + (size_t)n * NCOL;
    float f10 = p1[ch], f11 = p1[ch+1];
    float s10 = p1[PLN+ch], s11 = p1[PLN+ch+1];
    float f1t = 0.f, s1t = 0.f, wft = 0.f, wst = 0.f;
    if (tail){ f1t = p1[128]; s1t = p1[PLN+128]; wft = w3[128]; wst = w3[PLN+128]; }

    int beg = d_rowptr[n], end = d_rowptr[n + 1];
    float a0 = 0.f, a1 = 0.f, at = 0.f;

    int i = beg;
    for (; i + 4 <= end; i += 4){
        int2 e0 = d_edges[i],   e1 = d_edges[i+1];
        int2 e2 = d_edges[i+2], e3 = d_edges[i+3];
        const __half* q0 = d_P2h + (size_t)e0.x * P2S;
        const __half* q1 = d_P2h + (size_t)e1.x * P2S;
        const __half* q2 = d_P2h + (size_t)e2.x * P2S;
        const __half* q3 = d_P2h + (size_t)e3.x * P2S;
        uint32_t fu0 = *(const uint32_t*)(q0 + ch), su0 = *(const uint32_t*)(q0 + PLN + ch);
        uint32_t fu1 = *(const uint32_t*)(q1 + ch), su1 = *(const uint32_t*)(q1 + PLN + ch);
        uint32_t fu2 = *(const uint32_t*)(q2 + ch), su2 = *(const uint32_t*)(q2 + PLN + ch);
        uint32_t fu3 = *(const uint32_t*)(q3 + ch), su3 = *(const uint32_t*)(q3 + PLN + ch);
        float tf0=0,ts0=0,tf1=0,ts1=0,tf2=0,ts2=0,tf3=0,ts3=0;
        if (tail){
            tf0 = __half2float(q0[128]); ts0 = __half2float(q0[PLN+128]);
            tf1 = __half2float(q1[128]); ts1 = __half2float(q1[PLN+128]);
            tf2 = __half2float(q2[128]); ts2 = __half2float(q2[PLN+128]);
            tf3 = __half2float(q3[128]); ts3 = __half2float(q3[PLN+128]);
        }
        float ev0 = __int_as_float(e0.y), ev1 = __int_as_float(e1.y);
        float ev2 = __int_as_float(e2.y), ev3 = __int_as_float(e3.y);
        float2 f, s;
        f = __half22float2(*(__half2*)&fu0); s = __half22float2(*(__half2*)&su0);
        a0 += gact(f10 + f.x + ev0*wf0, s10 + s.x + ev0*ws0);
        a1 += gact(f11 + f.y + ev0*wf1, s11 + s.y + ev0*ws1);
        f = __half22float2(*(__half2*)&fu1); s = __half22float2(*(__half2*)&su1);
        a0 += gact(f10 + f.x + ev1*wf0, s10 + s.x + ev1*ws0);
        a1 += gact(f11 + f.y + ev1*wf1, s11 + s.y + ev1*ws1);
        f = __half22float2(*(__half2*)&fu2); s = __half22float2(*(__half2*)&su2);
        a0 += gact(f10 + f.x + ev2*wf0, s10 + s.x + ev2*ws0);
        a1 += gact(f11 + f.y + ev2*wf1, s11 + s.y + ev2*ws1);
        f = __half22float2(*(__half2*)&fu3); s = __half22float2(*(__half2*)&su3);
        a0 += gact(f10 + f.x + ev3*wf0, s10 + s.x + ev3*ws0);
        a1 += gact(f11 + f.y + ev3*wf1, s11 + s.y + ev3*ws1);
        if (tail){
            at += gact(f1t + tf0 + ev0*wft, s1t + ts0 + ev0*wst);
            at += gact(f1t + tf1 + ev1*wft, s1t + ts1 + ev1*wst);
            at += gact(f1t + tf2 + ev2*wft, s1t + ts2 + ev2*wst);
            at += gact(f1t + tf3 + ev3*wft, s1t + ts3 + ev3*wst);
        }
    }
    for (; i < end; i++){
        int2 e = d_edges[i];
        float ev = __int_as_float(e.y);
        const __half* q = d_P2h + (size_t)e.x * P2S;
        uint32_t fu = *(const uint32_t*)(q + ch), su = *(const uint32_t*)(q + PLN + ch);
        float2 f = __half22float2(*(__half2*)&fu);
        float2 s = __half22float2(*(__half2*)&su);
        a0 += gact(f10 + f.x + ev*wf0, s10 + s.x + ev*ws0);
        a1 += gact(f11 + f.y + ev*wf1, s11 + s.y + ev*ws1);
        if (tail)
            at += gact(f1t + __half2float(q[128]) + ev*wft,
                       s1t + __half2float(q[PLN+128]) + ev*wst);
    }

    float* xr = xn + (size_t)n * XS;
    const float* xcr = xc + (size_t)n * XS;
    float2 xv = *(const float2*)(xcr + ch);
    xv.x += a0; xv.y += a1;
    *(float2*)(xr + ch) = xv;
    if (tail) xr[128] = xcr[128] + at;
}

// ---- pooling + head ----
__global__ void zero_pool_kernel(){
    int idx = blockIdx.x * blockDim.x + threadIdx.x;
    if (idx < NUM_GRAPHS*PLN) d_gsum[idx] = 0.f;
    if (idx < NUM_GRAPHS)     d_gcnt[idx] = 0.f;
}
__global__ __launch_bounds__(256)
void pool_kernel(const float* __restrict__ x, const int* __restrict__ batch){
    int lane = threadIdx.x & 31, warp = threadIdx.x >> 5;
    int n = blockIdx.x * 8 + warp;
    int b = batch[n];
    const float* xr = x + (size_t)n * XS;
    float4 v = *(const float4*)(xr + lane*4);
    red4(&d_gsum[b*PLN + lane*4], v);
    if (lane == 0) atomicAdd(&d_gsum[b*PLN + 128], xr[128]);
    if (lane == 1) atomicAdd(&d_gcnt[b], 1.f);
}
__global__ void head_kernel(const float* __restrict__ Wfc, const float* __restrict__ bfc,
                            const float* __restrict__ Wout, const float* __restrict__ bout,
                            float* __restrict__ out){
    int g = blockIdx.x, t = threadIdx.x;
    __shared__ float row[C];
    __shared__ float red[256];
    if (t < C) row[t] = d_gsum[g*PLN + t] / fmaxf(d_gcnt[g], 1.f);
    __syncthreads();
    for (int l = 0; l < 3; l++){
        float y = 0.f;
        if (t < C){
            #pragma unroll 4
            for (int k = 0; k < C; k++) y = fmaf(row[k], Wfc[(l*C + k)*C + t], y);
            y += bfc[l*C + t];
        }
        __syncthreads();
        if (t < C) row[t] = y;
        __syncthreads();
    }
    red[t] = (t < C) ? row[t]*Wout[t] : 0.f;
    __syncthreads();
    for (int s = 128; s > 0; s >>= 1){ if (t < s) red[t] += red[t + s]; __syncthreads(); }
    if (t == 0) out[g] = red[0] + bout[0];
}

extern "C" void kernel_launch(void* const* d_in, const int* in_sizes, int n_in,
                              void* d_out, int out_size){
    const int*   atoms = (const int*)d_in[0];
    const float* pos   = (const float*)d_in[1];
    const int*   ei    = (const int*)d_in[2];
    const int*   batch = (const int*)d_in[3];
    const float* emb   = (const float*)d_in[4];
    const float* Wf    = (const float*)d_in[5];
    const float* bf    = (const float*)d_in[6];
    const float* Ws    = (const float*)d_in[7];
    const float* bs    = (const float*)d_in[8];
    const float* Wfc   = (const float*)d_in[9];
    const float* bfc   = (const float*)d_in[10];
    const float* Wout  = (const float*)d_in[11];
    const float* bout  = (const float*)d_in[12];
    float* out = (float*)d_out;

    cudaFuncSetAttribute(node_gemm_kernel,
                         cudaFuncAttributeMaxDynamicSharedMemorySize, GSMEM);

    float *xa, *xb;
    cudaGetSymbolAddress((void**)&xa, d_xa);
    cudaGetSymbolAddress((void**)&xb, d_xb);

    pack_wbN_kernel<<<(NLAYERS*2*2*5*NPG*32 + 255)/256, 256>>>(Wf, Ws);
    pack_bph_kernel<<<(NLAYERS*2*NPG + 255)/256, 256>>>(bf, bs);
    pack_w3_kernel<<<(NLAYERS*NCOL + 255)/256, 256>>>(Wf, Ws);
    init_x_kernel<<<(NROWS*XS + 255)/256, 256>>>(atoms, pos, emb);

    zero_cnt_kernel<<<(N_NODES + 255)/256, 256>>>();
    hist_kernel<<<(N_EDGES + 255)/256, 256>>>(ei);
    scan_kernel<<<1, 1024>>>();
    scatter_kernel<<<(N_EDGES + 255)/256, 256>>>(ei, pos);

    float* cur = xa;
    float* nxt = xb;
    for (int l = 0; l < NLAYERS; l++){
        node_gemm_kernel<<<dim3(NROWS/128, 2), 512, GSMEM>>>(cur, l);
        edge_csr_kernel<<<N_NODES/4, 256>>>(cur, nxt, l);
        float* tmp = cur; cur = nxt; nxt = tmp;
    }

    zero_pool_kernel<<<(NUM_GRAPHS*PLN + 255)/256, 256>>>();
    pool_kernel<<<N_NODES/8, 256>>>(cur, batch);
    head_kernel<<<NUM_GRAPHS, 256>>>(Wfc, bfc, Wout, bout, out);
}

// round 10
// speedup vs baseline: 1.0735x; 1.0735x over previous
#include <cuda_runtime.h>
#include <cuda_bf16.h>
#include <cuda_fp16.h>
#include <cstdint>
#include <math.h>

#define N_NODES   50000
#define NROWS     50048
#define N_EDGES   800000
#define NUM_GRAPHS 256
#define C         129
#define ZDIM      259
#define NLAYERS   5
#define XS        160
#define PLN       132
#define NCOL      264
#define NPG       288
#define P2S       320

// GEMM smem offsets
#define GSA    0
#define GSAL   43008
#define GSB    86016
#define GSSP   23040
#define GSBUF  46080
#define GSBI   178176
#define GSMEM  179328

__device__ __align__(16) __nv_bfloat16 d_wbN[NLAYERS*2*2*5*NPG*32];
__device__ float d_bph[NLAYERS*2*NPG];
__device__ float d_w3[NLAYERS*NCOL];
__device__ __align__(16) float d_xa[NROWS*XS];
__device__ __align__(16) float d_xb[NROWS*XS];
__device__ __align__(16) float  d_P1[(size_t)NROWS*NCOL];
__device__ __align__(16) __half d_P2h[(size_t)NROWS*P2S];
__device__ int   d_cnt[N_NODES];
__device__ int   d_rowptr[N_NODES + 1];
__device__ int   d_pos[N_NODES];
__device__ __align__(8) int2 d_edges[N_EDGES];
__device__ int   d_dh[256];
__device__ int   d_dpos[256];
__device__ int   d_order[N_NODES];
__device__ float d_gsum[NUM_GRAPHS*PLN];
__device__ float d_gcnt[NUM_GRAPHS];

// interleaved column mapping: col n -> group g=n>>2, plane pl=(n>>1)&1, chan j=2g+(n&1)
__device__ __host__ __forceinline__ void colmap(int n, int& pl, int& j){
    pl = (n >> 1) & 1;
    j  = 2*(n >> 2) + (n & 1);
}

__device__ __forceinline__ uint32_t smem_u32(const void* p){
    uint32_t a;
    asm("{ .reg .u64 t; cvta.to.shared.u64 t, %1; cvt.u32.u64 %0, t; }" : "=r"(a) : "l"(p));
    return a;
}
__device__ __forceinline__ void mma16816(float* d, uint32_t a0, uint32_t a1,
                                         uint32_t a2, uint32_t a3,
                                         uint32_t b0, uint32_t b1){
    asm volatile(
        "mma.sync.aligned.m16n8k16.row.col.f32.bf16.bf16.f32 "
        "{%0,%1,%2,%3}, {%4,%5,%6,%7}, {%8,%9}, {%0,%1,%2,%3};"
        : "+f"(d[0]), "+f"(d[1]), "+f"(d[2]), "+f"(d[3])
        : "r"(a0), "r"(a1), "r"(a2), "r"(a3), "r"(b0), "r"(b1));
}
__device__ __forceinline__ void cpasync16(uint32_t s, const void* g){
    asm volatile("cp.async.cg.shared.global [%0], [%1], 16;" :: "r"(s), "l"(g));
}
__device__ __forceinline__ void red4(float* p, float4 v){
    asm volatile("red.global.add.v4.f32 [%0], {%1,%2,%3,%4};"
                 :: "l"(p), "f"(v.x), "f"(v.y), "f"(v.z), "f"(v.w) : "memory");
}
__device__ __forceinline__ __half2 h2tanh_(__half2 x){
    uint32_t r, a = *(uint32_t*)&x;
    asm("tanh.approx.f16x2 %0, %1;" : "=r"(r) : "r"(a));
    return *(__half2*)&r;
}
__device__ __forceinline__ __half2 h2ex2_(__half2 x){
    uint32_t r, a = *(uint32_t*)&x;
    asm("ex2.approx.f16x2 %0, %1;" : "=r"(r) : "r"(a));
    return *(__half2*)&r;
}
__device__ __forceinline__ float sigf(float f){
    float t;
    asm("tanh.approx.f32 %0, %1;" : "=f"(t) : "f"(0.5f * f));
    return fmaf(0.5f, t, 0.5f);
}
__device__ __forceinline__ float gact(float f, float s){
    float sp = fmaxf(s, 0.f) + __logf(1.f + __expf(-fabsf(s)));
    return sigf(f) * sp;
}

// ---- prepack ----
__global__ void pack_wbN_kernel(const float* __restrict__ Wf, const float* __restrict__ Ws){
    int idx = blockIdx.x * blockDim.x + threadIdx.x;
    if (idx >= NLAYERS*2*2*5*NPG*32) return;
    int k  = idx & 31;
    int n  = (idx >> 5) % NPG;
    int kc = (idx / (32*NPG)) % 5;
    int sp = (idx / (32*NPG*5)) & 1;
    int hf = (idx / (32*NPG*5*2)) & 1;
    int l  = idx / (32*NPG*5*2*2);
    int kg = kc*32 + k;
    float w = 0.f;
    if (n < NCOL && kg < C){
        int pl, j; colmap(n, pl, j);
        if (j < C){
            int zi = hf ? (C + kg) : kg;
            const float* W = pl ? Ws : Wf;
            w = W[(l*ZDIM + zi)*C + j];
        }
    }
    __nv_bfloat16 hi = __float2bfloat16(w);
    d_wbN[idx] = sp ? __float2bfloat16(w - __bfloat162float(hi)) : hi;
}
__global__ void pack_bph_kernel(const float* __restrict__ bf, const float* __restrict__ bs){
    int idx = blockIdx.x * blockDim.x + threadIdx.x;
    if (idx >= NLAYERS*2*NPG) return;
    int n = idx % NPG, hf = (idx / NPG) & 1, l = idx / (2*NPG);
    float v = 0.f;
    if (hf == 0 && n < NCOL){
        int pl, j; colmap(n, pl, j);
        if (j < C) v = pl ? bs[l*C + j] : bf[l*C + j];
    }
    d_bph[idx] = v;
}
__global__ void pack_w3_kernel(const float* __restrict__ Wf, const float* __restrict__ Ws){
    int idx = blockIdx.x * blockDim.x + threadIdx.x;
    if (idx >= NLAYERS*NCOL) return;
    int n = idx % NCOL, l = idx / NCOL;
    int pl, j; colmap(n, pl, j);
    float v = 0.f;
    if (j < C){ const float* W = pl ? Ws : Wf; v = W[(l*ZDIM + 258)*C + j]; }
    d_w3[idx] = v;
}
__global__ void init_x_kernel(const int* __restrict__ atoms, const float* __restrict__ pos,
                              const float* __restrict__ emb){
    int idx = blockIdx.x * blockDim.x + threadIdx.x;
    if (idx >= NROWS*XS) return;
    int n = idx / XS, c = idx - n*XS;
    float v = 0.f;
    if (n < N_NODES){
        if (c < 128) v = emb[atoms[n]*128 + c];
        else if (c == 128) v = pos[n*3 + 2];
    }
    d_xa[idx] = v;
}

// ---- CSR build + degree-ordered schedule ----
__global__ void zero_cnt_kernel(){
    int i = blockIdx.x * blockDim.x + threadIdx.x;
    if (i < N_NODES) d_cnt[i] = 0;
    if (i < 256) d_dh[i] = 0;
}
__global__ void hist_kernel(const int* __restrict__ ei){
    int e = blockIdx.x * blockDim.x + threadIdx.x;
    if (e < N_EDGES) atomicAdd(&d_cnt[ei[N_EDGES + e]], 1);
}
__global__ void scan_kernel(){
    __shared__ int wsum[32];
    __shared__ int carry;
    int tid = threadIdx.x, lane = tid & 31, wid = tid >> 5;
    if (tid == 0) carry = 0;
    __syncthreads();
    for (int base = 0; base < N_NODES; base += 1024){
        int i = base + tid;
        int v = (i < N_NODES) ? d_cnt[i] : 0;
        int x = v;
        #pragma unroll
        for (int d = 1; d < 32; d <<= 1){
            int y = __shfl_up_sync(0xffffffffu, x, d);
            if (lane >= d) x += y;
        }
        if (lane == 31) wsum[wid] = x;
        __syncthreads();
        if (wid == 0){
            int s = wsum[lane];
            #pragma unroll
            for (int d = 1; d < 32; d <<= 1){
                int y = __shfl_up_sync(0xffffffffu, s, d);
                if (lane >= d) s += y;
            }
            wsum[lane] = s;
        }
        __syncthreads();
        int excl = x - v + (wid ? wsum[wid-1] : 0) + carry;
        if (i < N_NODES){ d_rowptr[i] = excl; d_pos[i] = excl; }
        __syncthreads();
        if (tid == 0) carry += wsum[31];
        __syncthreads();
    }
    if (threadIdx.x == 0) d_rowptr[N_NODES] = carry;
}
__global__ void scatter_kernel(const int* __restrict__ ei, const float* __restrict__ pos){
    int e = blockIdx.x * blockDim.x + threadIdx.x;
    if (e >= N_EDGES) return;
    int s = ei[e], d = ei[N_EDGES + e];
    float dx = pos[s*3]-pos[d*3], dy = pos[s*3+1]-pos[d*3+1], dz = pos[s*3+2]-pos[d*3+2];
    float eav = sqrtf(dx*dx + dy*dy + dz*dz);
    int p = atomicAdd(&d_pos[d], 1);
    d_edges[p] = make_int2(s, __float_as_int(eav));
}
__global__ void dhist_kernel(){
    int n = blockIdx.x * blockDim.x + threadIdx.x;
    if (n >= N_NODES) return;
    int d = min(d_cnt[n], 255);
    atomicAdd(&d_dh[d], 1);
}
__global__ void dscan_kernel(){
    if (threadIdx.x == 0){
        int acc = 0;
        for (int d = 255; d >= 0; d--){ d_dpos[d] = acc; acc += d_dh[d]; }
    }
}
__global__ void dorder_kernel(){
    int n = blockIdx.x * blockDim.x + threadIdx.x;
    if (n >= N_NODES) return;
    int d = min(d_cnt[n], 255);
    int p = atomicAdd(&d_dpos[d], 1);
    d_order[p] = n;
}

// ---- node GEMM ----
__global__ __launch_bounds__(512, 1)
void node_gemm_kernel(const float* __restrict__ xc, int layer){
    extern __shared__ __align__(16) char smem[];
    uint32_t sb = smem_u32(smem);
    int tid = threadIdx.x, lane = tid & 31, wid = tid >> 5;
    int r0 = lane >> 2, tin = lane & 3;
    int warpM = wid & 3, warpN = wid >> 2;
    int m0 = blockIdx.x * 128;
    int hf = blockIdx.y;

    const __nv_bfloat16* wbase = d_wbN + (size_t)((layer*2 + hf)*2) * 5*NPG*32;

    #pragma unroll
    for (int pc = 0; pc < 2; pc++){
        for (int i = tid; i < 2304; i += 512){
            int sp = i / 1152, rr = i % 1152, n = rr >> 2, kv = rr & 3;
            const void* g = wbase + ((size_t)sp*5 + pc)*NPG*32 + n*32 + kv*8;
            cpasync16(sb + GSB + pc*GSBUF + sp*GSSP + n*80 + kv*16, g);
        }
        asm volatile("cp.async.commit_group;" ::: "memory");
    }
    float* biS = (float*)(smem + GSBI);
    for (int i = tid; i < NPG; i += 512) biS[i] = d_bph[(layer*2 + hf)*NPG + i];

    {
        int row = tid >> 2, q = tid & 3;
        const float4* xr = (const float4*)(xc + (size_t)(m0 + row)*XS) + q*10;
        char* arow = smem + GSA + row*336 + q*80;
        #pragma unroll
        for (int j = 0; j < 10; j++){
            float4 v = xr[j];
            __nv_bfloat16 hx = __float2bfloat16(v.x), hy = __float2bfloat16(v.y);
            __nv_bfloat16 hz = __float2bfloat16(v.z), hw = __float2bfloat16(v.w);
            __nv_bfloat162 h0(hx, hy), h1(hz, hw);
            __nv_bfloat162 l0(__float2bfloat16(v.x - __bfloat162float(hx)),
                              __float2bfloat16(v.y - __bfloat162float(hy)));
            __nv_bfloat162 l1(__float2bfloat16(v.z - __bfloat162float(hz)),
                              __float2bfloat16(v.w - __bfloat162float(hw)));
            *(uint2*)(arow + j*8)        = make_uint2(*(uint32_t*)&h0, *(uint32_t*)&h1);
            *(uint2*)(arow + GSAL + j*8) = make_uint2(*(uint32_t*)&l0, *(uint32_t*)&l1);
        }
    }

    float acc[2][9][4];
    #pragma unroll
    for (int a = 0; a < 2; a++)
        #pragma unroll
        for (int b = 0; b < 9; b++)
            #pragma unroll
            for (int c = 0; c < 4; c++) acc[a][b][c] = 0.f;

    uint32_t aoff = (uint32_t)((warpM*32 + r0)*336 + tin*4);
    uint32_t boff = (uint32_t)((warpN*72 + r0)*80 + tin*4);

    for (int sc = 0; sc < 5; sc++){
        int buf = sc & 1;
        if (sc == 4) asm volatile("cp.async.wait_group 0;" ::: "memory");
        else         asm volatile("cp.async.wait_group 1;" ::: "memory");
        __syncthreads();
        const char* bbuf = smem + GSB + buf*GSBUF;
        #pragma unroll
        for (int ks = 0; ks < 2; ks++){
            uint32_t ka = (uint32_t)(sc*32 + ks*16)*2;
            const char* ap = smem + GSA + aoff + ka;
            uint32_t ah[2][4], al[2][4];
            #pragma unroll
            for (int mt = 0; mt < 2; mt++){
                const char* p = ap + mt*5376;
                ah[mt][0] = *(const uint32_t*)(p);
                ah[mt][1] = *(const uint32_t*)(p + 2688);
                ah[mt][2] = *(const uint32_t*)(p + 16);
                ah[mt][3] = *(const uint32_t*)(p + 2704);
                const char* q = p + GSAL;
                al[mt][0] = *(const uint32_t*)(q);
                al[mt][1] = *(const uint32_t*)(q + 2688);
                al[mt][2] = *(const uint32_t*)(q + 16);
                al[mt][3] = *(const uint32_t*)(q + 2704);
            }
            uint32_t kb = (uint32_t)ks*32;
            #pragma unroll
            for (int nt = 0; nt < 9; nt++){
                const char* bp = bbuf + boff + nt*640 + kb;
                uint32_t bh0 = *(const uint32_t*)(bp);
                uint32_t bh1 = *(const uint32_t*)(bp + 16);
                uint32_t bl0 = *(const uint32_t*)(bp + GSSP);
                uint32_t bl1 = *(const uint32_t*)(bp + GSSP + 16);
                mma16816(acc[0][nt], ah[0][0], ah[0][1], ah[0][2], ah[0][3], bh0, bh1);
                mma16816(acc[1][nt], ah[1][0], ah[1][1], ah[1][2], ah[1][3], bh0, bh1);
                mma16816(acc[0][nt], al[0][0], al[0][1], al[0][2], al[0][3], bh0, bh1);
                mma16816(acc[1][nt], al[1][0], al[1][1], al[1][2], al[1][3], bh0, bh1);
                mma16816(acc[0][nt], ah[0][0], ah[0][1], ah[0][2], ah[0][3], bl0, bl1);
                mma16816(acc[1][nt], ah[1][0], ah[1][1], ah[1][2], ah[1][3], bl0, bl1);
            }
        }
        __syncthreads();
        if (sc < 3){
            int nc = sc + 2;
            for (int i = tid; i < 2304; i += 512){
                int sp = i / 1152, rr = i % 1152, n = rr >> 2, kv = rr & 3;
                const void* g = wbase + ((size_t)sp*5 + nc)*NPG*32 + n*32 + kv*8;
                cpasync16(sb + GSB + buf*GSBUF + sp*GSSP + n*80 + kv*16, g);
            }
            asm volatile("cp.async.commit_group;" ::: "memory");
        }
    }

    #pragma unroll
    for (int mt = 0; mt < 2; mt++){
        #pragma unroll
        for (int nt = 0; nt < 9; nt++){
            int col = warpN*72 + nt*8 + tin*2;
            if (col >= NCOL) continue;
            float b0 = biS[col], b1 = biS[col + 1];
            #pragma unroll
            for (int h = 0; h < 2; h++){
                int row = m0 + warpM*32 + mt*16 + r0 + h*8;
                float v0 = acc[mt][nt][2*h] + b0;
                float v1 = acc[mt][nt][2*h+1] + b1;
                if (hf == 0){
                    *(float2*)(d_P1 + (size_t)row*NCOL + col) = make_float2(v0, v1);
                } else {
                    *(__half2*)(d_P2h + (size_t)row*P2S + col) = __floats2half2_rn(v0, v1);
                }
            }
        }
    }
}

// ---- edge phase: warp-per-node, interleaved uint4 gather, f16x2 transcendentals ----
__global__ __launch_bounds__(256)
void edge_csr_kernel(const float* __restrict__ xc, float* __restrict__ xn, int layer){
    int lane = threadIdx.x & 31, warp = threadIdx.x >> 5;
    int n = d_order[blockIdx.x * 8 + warp];
    int cb = lane * 8;
    const float* w3 = d_w3 + layer * NCOL;
    const float* p1 = d_P1 + (size_t)n * NCOL;
    float4 pa = *(const float4*)(p1 + cb);
    float4 pb = *(const float4*)(p1 + cb + 4);
    float4 wa = *(const float4*)(w3 + cb);
    float4 wb = *(const float4*)(w3 + cb + 4);
    float f1h0=0.5f*pa.x, f1h1=0.5f*pa.y, f1h2=0.5f*pb.x, f1h3=0.5f*pb.y;
    float wfh0=0.5f*wa.x, wfh1=0.5f*wa.y, wfh2=0.5f*wb.x, wfh3=0.5f*wb.y;
    float s10=pa.z, s11=pa.w, s12=pb.z, s13=pb.w;
    float ws0=wa.z, ws1=wa.w, ws2=wb.z, ws3=wb.w;
    float f1t=0.f, s1t=0.f, wft=0.f, wst=0.f;
    if (lane == 0){ f1t=p1[256]; s1t=p1[258]; wft=w3[256]; wst=w3[258]; }
    const __half2 h05 = __float2half2_rn(0.5f);
    int beg = d_rowptr[n], end = d_rowptr[n + 1];
    float a0=0.f, a1=0.f, a2=0.f, a3=0.f, at=0.f;

    #pragma unroll 2
    for (int i = beg; i < end; i++){
        int2 e = d_edges[i];
        float ev = __int_as_float(e.y);
        const __half* q = d_P2h + (size_t)e.x * P2S;
        uint4 w = *(const uint4*)(q + cb);
        __half2 cfA = __floats2half2_rn(fmaf(ev, wfh0, f1h0), fmaf(ev, wfh1, f1h1));
        __half2 cfB = __floats2half2_rn(fmaf(ev, wfh2, f1h2), fmaf(ev, wfh3, f1h3));
        float2 t01 = __half22float2(h2tanh_(__hfma2(*(__half2*)&w.x, h05, cfA)));
        float2 t23 = __half22float2(h2tanh_(__hfma2(*(__half2*)&w.z, h05, cfB)));
        float2 sy = __half22float2(*(__half2*)&w.y);
        float2 sw2 = __half22float2(*(__half2*)&w.w);
        float s0 = fmaf(ev, ws0, s10) + sy.x;
        float s1 = fmaf(ev, ws1, s11) + sy.y;
        float s2 = fmaf(ev, ws2, s12) + sw2.x;
        float s3 = fmaf(ev, ws3, s13) + sw2.y;
        __half2 uiA = __floats2half2_rn(fabsf(s0)*-1.44269504f, fabsf(s1)*-1.44269504f);
        __half2 uiB = __floats2half2_rn(fabsf(s2)*-1.44269504f, fabsf(s3)*-1.44269504f);
        float2 u01 = __half22float2(h2ex2_(uiA));
        float2 u23 = __half22float2(h2ex2_(uiB));
        float sp0 = fmaxf(s0, 0.f) + __logf(1.f + u01.x);
        float sp1 = fmaxf(s1, 0.f) + __logf(1.f + u01.y);
        float sp2 = fmaxf(s2, 0.f) + __logf(1.f + u23.x);
        float sp3 = fmaxf(s3, 0.f) + __logf(1.f + u23.y);
        a0 = fmaf(fmaf(0.5f, t01.x, 0.5f), sp0, a0);
        a1 = fmaf(fmaf(0.5f, t01.y, 0.5f), sp1, a1);
        a2 = fmaf(fmaf(0.5f, t23.x, 0.5f), sp2, a2);
        a3 = fmaf(fmaf(0.5f, t23.y, 0.5f), sp3, a3);
        if (lane == 0){
            uint2 tw = *(const uint2*)(q + 256);
            float2 tf = __half22float2(*(__half2*)&tw.x);
            float2 ts = __half22float2(*(__half2*)&tw.y);
            at += gact(f1t + tf.x + ev*wft, s1t + ts.x + ev*wst);
        }
    }

    float* xr = xn + (size_t)n * XS;
    const float* xcr = xc + (size_t)n * XS;
    float4 xv = *(const float4*)(xcr + lane*4);
    xv.x += a0; xv.y += a1; xv.z += a2; xv.w += a3;
    *(float4*)(xr + lane*4) = xv;
    if (lane == 0) xr[128] = xcr[128] + at;
}

// ---- pooling + head ----
__global__ void zero_pool_kernel(){
    int idx = blockIdx.x * blockDim.x + threadIdx.x;
    if (idx < NUM_GRAPHS*PLN) d_gsum[idx] = 0.f;
    if (idx < NUM_GRAPHS)     d_gcnt[idx] = 0.f;
}
__global__ __launch_bounds__(256)
void pool_kernel(const float* __restrict__ x, const int* __restrict__ batch){
    int lane = threadIdx.x & 31, warp = threadIdx.x >> 5;
    int n = blockIdx.x * 8 + warp;
    int b = batch[n];
    const float* xr = x + (size_t)n * XS;
    float4 v = *(const float4*)(xr + lane*4);
    red4(&d_gsum[b*PLN + lane*4], v);
    if (lane == 0) atomicAdd(&d_gsum[b*PLN + 128], xr[128]);
    if (lane == 1) atomicAdd(&d_gcnt[b], 1.f);
}
__global__ void head_kernel(const float* __restrict__ Wfc, const float* __restrict__ bfc,
                            const float* __restrict__ Wout, const float* __restrict__ bout,
                            float* __restrict__ out){
    int g = blockIdx.x, t = threadIdx.x;
    __shared__ float row[C];
    __shared__ float red[256];
    if (t < C) row[t] = d_gsum[g*PLN + t] / fmaxf(d_gcnt[g], 1.f);
    __syncthreads();
    for (int l = 0; l < 3; l++){
        float y = 0.f;
        if (t < C){
            #pragma unroll 4
            for (int k = 0; k < C; k++) y = fmaf(row[k], Wfc[(l*C + k)*C + t], y);
            y += bfc[l*C + t];
        }
        __syncthreads();
        if (t < C) row[t] = y;
        __syncthreads();
    }
    red[t] = (t < C) ? row[t]*Wout[t] : 0.f;
    __syncthreads();
    for (int s = 128; s > 0; s >>= 1){ if (t < s) red[t] += red[t + s]; __syncthreads(); }
    if (t == 0) out[g] = red[0] + bout[0];
}

extern "C" void kernel_launch(void* const* d_in, const int* in_sizes, int n_in,
                              void* d_out, int out_size){
    const int*   atoms = (const int*)d_in[0];
    const float* pos   = (const float*)d_in[1];
    const int*   ei    = (const int*)d_in[2];
    const int*   batch = (const int*)d_in[3];
    const float* emb   = (const float*)d_in[4];
    const float* Wf    = (const float*)d_in[5];
    const float* bf    = (const float*)d_in[6];
    const float* Ws    = (const float*)d_in[7];
    const float* bs    = (const float*)d_in[8];
    const float* Wfc   = (const float*)d_in[9];
    const float* bfc   = (const float*)d_in[10];
    const float* Wout  = (const float*)d_in[11];
    const float* bout  = (const float*)d_in[12];
    float* out = (float*)d_out;

    cudaFuncSetAttribute(node_gemm_kernel,
                         cudaFuncAttributeMaxDynamicSharedMemorySize, GSMEM);

    float *xa, *xb;
    cudaGetSymbolAddress((void**)&xa, d_xa);
    cudaGetSymbolAddress((void**)&xb, d_xb);

    pack_wbN_kernel<<<(NLAYERS*2*2*5*NPG*32 + 255)/256, 256>>>(Wf, Ws);
    pack_bph_kernel<<<(NLAYERS*2*NPG + 255)/256, 256>>>(bf, bs);
    pack_w3_kernel<<<(NLAYERS*NCOL + 255)/256, 256>>>(Wf, Ws);
    init_x_kernel<<<(NROWS*XS + 255)/256, 256>>>(atoms, pos, emb);

    zero_cnt_kernel<<<(N_NODES + 255)/256, 256>>>();
    hist_kernel<<<(N_EDGES + 255)/256, 256>>>(ei);
    scan_kernel<<<1, 1024>>>();
    scatter_kernel<<<(N_EDGES + 255)/256, 256>>>(ei, pos);
    dhist_kernel<<<(N_NODES + 255)/256, 256>>>();
    dscan_kernel<<<1, 32>>>();
    dorder_kernel<<<(N_NODES + 255)/256, 256>>>();

    float* cur = xa;
    float* nxt = xb;
    for (int l = 0; l < NLAYERS; l++){
        node_gemm_kernel<<<dim3(NROWS/128, 2), 512, GSMEM>>>(cur, l);
        edge_csr_kernel<<<N_NODES/8, 256>>>(cur, nxt, l);
        float* tmp = cur; cur = nxt; nxt = tmp;
    }

    zero_pool_kernel<<<(NUM_GRAPHS*PLN + 255)/256, 256>>>();
    pool_kernel<<<N_NODES/8, 256>>>(cur, batch);
    head_kernel<<<NUM_GRAPHS, 256>>>(Wfc, bfc, Wout, bout, out);
}